// round 12
// baseline (speedup 1.0000x reference)
#include <cuda_runtime.h>
#include <cuda_fp16.h>
#include <cstdint>

namespace {
constexpr int Tlen = 4096;
constexpr int IN   = 8;
constexpr int H    = 64;
constexpr int NB   = 4;
constexpr int NTHR = 256;   // 8 warps, each owns 2 m-tiles
constexpr int NBLK = 128;

using u32 = unsigned int;

constexpr int PB = 152;  // halves per B row (304 B pitch); k: 0-63 h0, 64-71 x, 72-79 z, 80-143 h1, 144-151 z

__device__ __forceinline__ float tanh_fast(float x) {
  float y;
  asm("tanh.approx.f32 %0, %1;" : "=f"(y) : "f"(x));
  return y;
}
__device__ __forceinline__ float sigmoid_fast(float x) {
  return fmaf(0.5f, tanh_fast(0.5f * x), 0.5f);
}
__device__ __forceinline__ u32 smem_u32(const void* p) {
  u32 a;
  asm("{ .reg .u64 t; cvta.to.shared.u64 t, %1; cvt.u32.u64 %0, t; }" : "=r"(a) : "l"(p));
  return a;
}
__device__ __forceinline__ void ldsm_x2(u32& r0, u32& r1, u32 addr) {
  asm volatile("ldmatrix.sync.aligned.m8n8.x2.shared.b16 {%0,%1}, [%2];"
               : "=r"(r0), "=r"(r1) : "r"(addr));
}
__device__ __forceinline__ void mma16816(float& c0, float& c1, float& c2, float& c3,
                                         const u32* a, u32 b0, u32 b1) {
  asm volatile(
      "mma.sync.aligned.m16n8k16.row.col.f32.f16.f16.f32 "
      "{%0,%1,%2,%3}, {%4,%5,%6,%7}, {%8,%9}, {%0,%1,%2,%3};"
      : "+f"(c0), "+f"(c1), "+f"(c2), "+f"(c3)
      : "r"(a[0]), "r"(a[1]), "r"(a[2]), "r"(a[3]), "r"(b0), "r"(b1));
}
__device__ __forceinline__ u32 pack2(float lo, float hi) {
  __half2 h = __floats2half2_rn(lo, hi);
  return *reinterpret_cast<u32*>(&h);
}
}  // namespace

__global__ __launch_bounds__(NTHR, 1) void lstm2_hmma3_kernel(
    const float* __restrict__ x,
    const float* __restrict__ Wih0, const float* __restrict__ Whh0,
    const float* __restrict__ bih0, const float* __restrict__ bhh0,
    const float* __restrict__ Wih1, const float* __restrict__ Whh1,
    const float* __restrict__ bih1, const float* __restrict__ bhh1,
    const float* __restrict__ fcw, const float* __restrict__ fcb,
    float* __restrict__ out) {
  __shared__ __align__(16) unsigned short B[2][8 * PB];   // [buf][n][k] merged operand
  __shared__ __align__(16) float GW[8][2][2][4][4][4];    // [warp][tile][layer][u][col][gate]
  __shared__ float H1F[256];
  __shared__ float FCW[H];

  const int tid  = threadIdx.x;
  const int w    = tid >> 5;
  const int lane = tid & 31;
  const int b0   = blockIdx.x * NB;
  const int rq   = lane >> 2;
  const int cq   = (lane & 3) * 2;

  for (int i = tid; i < 2 * 8 * PB; i += NTHR) (&B[0][0])[i] = 0;
  if (tid < H) FCW[tid] = fcw[tid];

  // ---- A fragments: warp w owns tiles T = 2w, 2w+1 (gate-interleaved rows) ----
  u32 A0f[2][5][4], A1f[2][8][4];
  {
#pragma unroll
    for (int tt = 0; tt < 2; ++tt) {
      const int T = w * 2 + tt;
      auto wrow = [&](int r) { return (r & 3) * 64 + T * 4 + (r >> 2); };
      auto a0e = [&](int r, int k) -> float {  // k = merged-B k coord
        int g = wrow(r);
        if (k < 64) return Whh0[g * H + k];
        if (k < 72) return Wih0[g * IN + (k - 64)];
        return 0.0f;
      };
      auto a1e = [&](int r, int k) -> float {
        int g = wrow(r);
        if (k < 64) return Wih1[g * H + k];
        if (k >= 80 && k < 144) return Whh1[g * H + (k - 80)];
        return 0.0f;
      };
#pragma unroll
      for (int kf = 0; kf < 5; ++kf) {
        const int c = kf * 16 + cq;
        A0f[tt][kf][0] = pack2(a0e(rq, c),         a0e(rq, c + 1));
        A0f[tt][kf][1] = pack2(a0e(rq + 8, c),     a0e(rq + 8, c + 1));
        A0f[tt][kf][2] = pack2(a0e(rq, c + 8),     a0e(rq, c + 9));
        A0f[tt][kf][3] = pack2(a0e(rq + 8, c + 8), a0e(rq + 8, c + 9));
      }
#pragma unroll
      for (int q = 0; q < 8; ++q) {  // l1 kf list: 0,1,2,3,5,6,7,8
        const int kf = (q < 4) ? q : q + 1;
        const int c = kf * 16 + cq;
        A1f[tt][q][0] = pack2(a1e(rq, c),         a1e(rq, c + 1));
        A1f[tt][q][1] = pack2(a1e(rq + 8, c),     a1e(rq + 8, c + 1));
        A1f[tt][q][2] = pack2(a1e(rq, c + 8),     a1e(rq, c + 9));
        A1f[tt][q][3] = pack2(a1e(rq + 8, c + 8), a1e(rq + 8, c + 9));
      }
    }
  }

  // ---- pointwise tasks: per lane, one (layer, u, b) per tile ----
  const int tl = lane >> 4;          // layer
  const int tu = (lane >> 2) & 3;    // unit within tile
  const int tb = lane & 3;           // batch
  float4 bq[2];
  float cst[2] = {0.0f, 0.0f};
  int tj[2];
  {
    const float* bi = tl ? bih1 : bih0;
    const float* bh = tl ? bhh1 : bhh0;
#pragma unroll
    for (int tt = 0; tt < 2; ++tt) {
      tj[tt] = (w * 2 + tt) * 4 + tu;
      const int j = tj[tt];
      bq[tt] = make_float4(bi[j] + bh[j], bi[64 + j] + bh[64 + j],
                           bi[128 + j] + bh[128 + j], bi[192 + j] + bh[192 + j]);
    }
  }

  // ---- x loader: warp 7, lane = b*8 + i ----
  const bool isL = (w == 7);
  const int xb_ = lane >> 3, xi = lane & 7;
  const long xbase = (long)(b0 + xb_) * Tlen * IN + xi;
  if (isL) {
    B[0][xb_ * PB + 64 + xi] = __half_as_ushort(__float2half_rn(x[xbase]));
  }
  float xcur = isL ? __ldg(&x[xbase + IN]) : 0.0f;  // x(1)
  __syncthreads();

  const u32 lrow = (lane & 7) * (PB * 2) + ((lane >> 3) & 1) * 16;
  const u32 sBa = smem_u32(&B[0][0]) + lrow, sBb = smem_u32(&B[1][0]) + lrow;

  int cur = 0;

#pragma unroll 1
  for (int t = 0; t <= Tlen; ++t) {
    const int nxt = cur ^ 1;
    float xnext = 0.0f;
    if (isL && t + 2 < Tlen) xnext = __ldg(&x[xbase + (long)(t + 2) * IN]);

    // ---- shared B fragments: 9 ldsm.x2 over merged buffer ----
    const u32 ab = cur ? sBb : sBa;
    u32 bf[9][2];
#pragma unroll
    for (int kf = 0; kf < 9; ++kf) ldsm_x2(bf[kf][0], bf[kf][1], ab + kf * 32);

    // ---- MMAs, 2 tiles, split accumulator chains ----
#pragma unroll
    for (int tt = 0; tt < 2; ++tt) {
      float p0 = 0.f, p1 = 0.f, p2 = 0.f, p3 = 0.f;   // l0 kf 0..2
      float q0 = 0.f, q1 = 0.f, q2 = 0.f, q3 = 0.f;   // l0 kf 3..4
      mma16816(p0, p1, p2, p3, A0f[tt][0], bf[0][0], bf[0][1]);
      mma16816(q0, q1, q2, q3, A0f[tt][3], bf[3][0], bf[3][1]);
      mma16816(p0, p1, p2, p3, A0f[tt][1], bf[1][0], bf[1][1]);
      mma16816(q0, q1, q2, q3, A0f[tt][4], bf[4][0], bf[4][1]);
      mma16816(p0, p1, p2, p3, A0f[tt][2], bf[2][0], bf[2][1]);

      float r0 = 0.f, r1 = 0.f, r2 = 0.f, r3 = 0.f;   // l1 q 0..3 (kf 0..3)
      float s0 = 0.f, s1 = 0.f, s2 = 0.f, s3 = 0.f;   // l1 q 4..7 (kf 5..8)
#pragma unroll
      for (int q = 0; q < 4; ++q) {
        const int kfa = q, kfb = q + 5;
        mma16816(r0, r1, r2, r3, A1f[tt][q],     bf[kfa][0], bf[kfa][1]);
        mma16816(s0, s1, s2, s3, A1f[tt][q + 4], bf[kfb][0], bf[kfb][1]);
      }

      if ((lane & 3) < 2) {
        const int u = rq >> 2, g = rq & 3;
        GW[w][tt][0][u][cq][g]         = p0 + q0;
        GW[w][tt][0][u][cq + 1][g]     = p1 + q1;
        GW[w][tt][0][u + 2][cq][g]     = p2 + q2;
        GW[w][tt][0][u + 2][cq + 1][g] = p3 + q3;
        GW[w][tt][1][u][cq][g]         = r0 + s0;
        GW[w][tt][1][u][cq + 1][g]     = r1 + s1;
        GW[w][tt][1][u + 2][cq][g]     = r2 + s2;
        GW[w][tt][1][u + 2][cq + 1][g] = r3 + s3;
      }
    }
    __syncwarp();

    // ---- pointwise: 2 tasks per lane ----
#pragma unroll
    for (int tt = 0; tt < 2; ++tt) {
      const float4 gv = *reinterpret_cast<const float4*>(&GW[w][tt][tl][tu][tb][0]);
      const bool act = tl ? (t > 0) : (t < Tlen);
      if (act) {
        float gi = sigmoid_fast(gv.x + bq[tt].x);
        float gf = sigmoid_fast(gv.y + bq[tt].y);
        float gg = tanh_fast(gv.z + bq[tt].z);
        float go = sigmoid_fast(gv.w + bq[tt].w);
        cst[tt] = fmaf(gf, cst[tt], gi * gg);
        float hv = go * tanh_fast(cst[tt]);
        if (tl == 0) {
          B[nxt][tb * PB + tj[tt]] = __half_as_ushort(__float2half_rn(hv));
        } else if (t < Tlen) {
          B[nxt][tb * PB + 80 + tj[tt]] = __half_as_ushort(__float2half_rn(hv));
        } else {
          H1F[tj[tt] * 4 + tb] = hv;
        }
      }
    }
    if (isL && t + 1 < Tlen) {
      B[nxt][xb_ * PB + 64 + xi] = __half_as_ushort(__float2half_rn(xcur));
      xcur = xnext;
    }
    __syncthreads();
    cur = nxt;
  }

  // ---- FC epilogue ----
  if (tid < NB) {
    float acc = fcb[0];
#pragma unroll 16
    for (int j = 0; j < H; ++j) acc = fmaf(H1F[j * 4 + tid], FCW[j], acc);
    out[b0 + tid] = 1.0f / (1.0f + __expf(-acc));
  }
}

extern "C" void kernel_launch(void* const* d_in, const int* in_sizes, int n_in,
                              void* d_out, int out_size) {
  const float* x    = (const float*)d_in[0];
  const float* Wih0 = (const float*)d_in[1];
  const float* Whh0 = (const float*)d_in[2];
  const float* bih0 = (const float*)d_in[3];
  const float* bhh0 = (const float*)d_in[4];
  const float* Wih1 = (const float*)d_in[5];
  const float* Whh1 = (const float*)d_in[6];
  const float* bih1 = (const float*)d_in[7];
  const float* bhh1 = (const float*)d_in[8];
  const float* fcw  = (const float*)d_in[9];
  const float* fcb  = (const float*)d_in[10];
  float* out = (float*)d_out;

  lstm2_hmma3_kernel<<<NBLK, NTHR>>>(x, Wih0, Whh0, bih0, bhh0, Wih1, Whh1,
                                     bih1, bhh1, fcw, fcb, out);
}

// round 13
// speedup vs baseline: 1.1795x; 1.1795x over previous
#include <cuda_runtime.h>
#include <cuda_fp16.h>
#include <cstdint>

namespace {
constexpr int Tlen = 4096;
constexpr int IN   = 8;
constexpr int H    = 64;
constexpr int NB   = 4;
constexpr int NTHR = 512;   // warps 0-7: layer0 group, 8-15: layer1 group
constexpr int NBLK = 128;

using u32 = unsigned int;

constexpr int PH = 72;  // h ring row pitch (halves) = 144 B, ldsm conflict-free
constexpr int PX = 40;  // x ring row pitch (halves) = 80 B

#define BARSYNC(id, cnt) asm volatile("bar.sync %0, %1;" ::"r"(id), "r"(cnt) : "memory")
#define BARARR(id, cnt)  asm volatile("bar.arrive %0, %1;" ::"r"(id), "r"(cnt) : "memory")
// ids: 1=INT0, 2=INT1, 3+p=FULL[p], 5+p=FREE[p]

__device__ __forceinline__ float tanh_fast(float x) {
  float y;
  asm("tanh.approx.f32 %0, %1;" : "=f"(y) : "f"(x));
  return y;
}
__device__ __forceinline__ float sigmoid_fast(float x) {
  return fmaf(0.5f, tanh_fast(0.5f * x), 0.5f);
}
__device__ __forceinline__ u32 smem_u32(const void* p) {
  u32 a;
  asm("{ .reg .u64 t; cvta.to.shared.u64 t, %1; cvt.u32.u64 %0, t; }" : "=r"(a) : "l"(p));
  return a;
}
__device__ __forceinline__ void ldsm_x2(u32& r0, u32& r1, u32 addr) {
  asm volatile("ldmatrix.sync.aligned.m8n8.x2.shared.b16 {%0,%1}, [%2];"
               : "=r"(r0), "=r"(r1) : "r"(addr));
}
__device__ __forceinline__ void mma16816(float& c0, float& c1, float& c2, float& c3,
                                         const u32* a, u32 b0, u32 b1) {
  asm volatile(
      "mma.sync.aligned.m16n8k16.row.col.f32.f16.f16.f32 "
      "{%0,%1,%2,%3}, {%4,%5,%6,%7}, {%8,%9}, {%0,%1,%2,%3};"
      : "+f"(c0), "+f"(c1), "+f"(c2), "+f"(c3)
      : "r"(a[0]), "r"(a[1]), "r"(a[2]), "r"(a[3]), "r"(b0), "r"(b1));
}
__device__ __forceinline__ u32 pack2(float lo, float hi) {
  __half2 h = __floats2half2_rn(lo, hi);
  return *reinterpret_cast<u32*>(&h);
}
}  // namespace

__global__ __launch_bounds__(NTHR, 1) void lstm2_ws_kernel(
    const float* __restrict__ x,
    const float* __restrict__ Wih0, const float* __restrict__ Whh0,
    const float* __restrict__ bih0, const float* __restrict__ bhh0,
    const float* __restrict__ Wih1, const float* __restrict__ Whh1,
    const float* __restrict__ bih1, const float* __restrict__ bhh1,
    const float* __restrict__ fcw, const float* __restrict__ fcb,
    float* __restrict__ out) {
  __shared__ __align__(16) unsigned short H0B[2][8 * PH];  // h0 ring [slot][n][k]
  __shared__ __align__(16) unsigned short H1B[2][8 * PH];  // h1 ring (L1-private)
  __shared__ __align__(16) unsigned short XB[2][8 * PX];   // x ring
  __shared__ __align__(16) float GW[16][2][4][4][4];       // [warp][tile][u][col][gate]
  __shared__ float H1F[256];
  __shared__ float FCW[H];

  const int tid  = threadIdx.x;
  const int w    = tid >> 5;
  const int lane = tid & 31;
  const int b0   = blockIdx.x * NB;
  const int rq   = lane >> 2;
  const int cq   = (lane & 3) * 2;
  const bool g0  = (w < 8);
  const int wl   = g0 ? w : w - 8;

  // zero rings
  for (int i = tid; i < 2 * 8 * PH; i += NTHR) { (&H0B[0][0])[i] = 0; (&H1B[0][0])[i] = 0; }
  for (int i = tid; i < 2 * 8 * PX; i += NTHR) (&XB[0][0])[i] = 0;
  if (tid < H) FCW[tid] = fcw[tid];
  if (g0 && wl == 7) {  // prestage x(0) into XB[0]
    XB[0][(lane >> 3) * PX + (lane & 7)] =
        __half_as_ushort(__float2half_rn(x[(long)(b0 + (lane >> 3)) * Tlen * IN + (lane & 7)]));
  }

  // per-lane pointwise task: tile tt, unit tu, batch tb  (layer = group)
  const int tt_ = lane >> 4, tu = (lane >> 2) & 3, tb = lane & 3;
  const int tj  = (wl * 2 + tt_) * 4 + tu;  // unit 0..63
  float4 bq;
  {
    const float* bi = g0 ? bih0 : bih1;
    const float* bh = g0 ? bhh0 : bhh1;
    bq = make_float4(bi[tj] + bh[tj], bi[64 + tj] + bh[64 + tj],
                     bi[128 + tj] + bh[128 + tj], bi[192 + tj] + bh[192 + tj]);
  }

  const u32 lrH = (lane & 7) * (PH * 2) + ((lane >> 3) & 1) * 16;
  const u32 lrX = (lane & 7) * (PX * 2) + ((lane >> 3) & 1) * 16;
  const u32 h0a[2] = {smem_u32(&H0B[0][0]) + lrH, smem_u32(&H0B[1][0]) + lrH};
  const u32 h1a[2] = {smem_u32(&H1B[0][0]) + lrH, smem_u32(&H1B[1][0]) + lrH};
  const u32 xba[2] = {smem_u32(&XB[0][0]) + lrX, smem_u32(&XB[1][0]) + lrX};

  __syncthreads();

  if (g0) {
    // ================= LAYER-0 GROUP =================
    u32 A0[2][5][4];
#pragma unroll
    for (int tt = 0; tt < 2; ++tt) {
      const int T = wl * 2 + tt;
      auto wrow = [&](int r) { return (r & 3) * 64 + T * 4 + (r >> 2); };
      auto ae = [&](int r, int k) -> float {
        int g = wrow(r);
        if (k < 64) return Whh0[g * H + k];
        if (k < 72) return Wih0[g * IN + (k - 64)];
        return 0.0f;
      };
#pragma unroll
      for (int kf = 0; kf < 5; ++kf) {
        const int c = kf * 16 + cq;
        A0[tt][kf][0] = pack2(ae(rq, c),         ae(rq, c + 1));
        A0[tt][kf][1] = pack2(ae(rq + 8, c),     ae(rq + 8, c + 1));
        A0[tt][kf][2] = pack2(ae(rq, c + 8),     ae(rq, c + 9));
        A0[tt][kf][3] = pack2(ae(rq + 8, c + 8), ae(rq + 8, c + 9));
      }
    }
    const bool isL = (wl == 7);
    const int xb_ = lane >> 3, xi = lane & 7;
    const long xbase = (long)(b0 + xb_) * Tlen * IN + xi;
    float xcur = isL ? __ldg(&x[xbase + IN]) : 0.0f;  // x(1)
    float cst = 0.0f;

#pragma unroll 1
    for (int t = 0; t < Tlen; ++t) {
      const int cur = t & 1, rd = cur ^ 1;
      float xnext = 0.0f;
      if (isL && t + 2 < Tlen) xnext = __ldg(&x[xbase + (long)(t + 2) * IN]);

      u32 bf[5][2];
#pragma unroll
      for (int kf = 0; kf < 4; ++kf) ldsm_x2(bf[kf][0], bf[kf][1], h0a[rd] + kf * 32);
      ldsm_x2(bf[4][0], bf[4][1], xba[cur]);

#pragma unroll
      for (int tt = 0; tt < 2; ++tt) {
        float p0 = 0.f, p1 = 0.f, p2 = 0.f, p3 = 0.f;
        float q0 = 0.f, q1 = 0.f, q2 = 0.f, q3 = 0.f;
        mma16816(p0, p1, p2, p3, A0[tt][0], bf[0][0], bf[0][1]);
        mma16816(q0, q1, q2, q3, A0[tt][3], bf[3][0], bf[3][1]);
        mma16816(p0, p1, p2, p3, A0[tt][1], bf[1][0], bf[1][1]);
        mma16816(q0, q1, q2, q3, A0[tt][4], bf[4][0], bf[4][1]);
        mma16816(p0, p1, p2, p3, A0[tt][2], bf[2][0], bf[2][1]);
        if ((lane & 3) < 2) {
          const int u = rq >> 2, g = rq & 3;
          GW[w][tt][u][cq][g]         = p0 + q0;
          GW[w][tt][u][cq + 1][g]     = p1 + q1;
          GW[w][tt][u + 2][cq][g]     = p2 + q2;
          GW[w][tt][u + 2][cq + 1][g] = p3 + q3;
        }
      }
      __syncwarp();
      const float4 gv = *reinterpret_cast<const float4*>(&GW[w][tt_][tu][tb][0]);
      BARSYNC(5 + cur, 512);  // FREE: l1 done reading slot cur (from t-2)
      {
        float gi = sigmoid_fast(gv.x + bq.x);
        float gf = sigmoid_fast(gv.y + bq.y);
        float gg = tanh_fast(gv.z + bq.z);
        float go = sigmoid_fast(gv.w + bq.w);
        cst = fmaf(gf, cst, gi * gg);
        H0B[cur][tb * PH + tj] = __half_as_ushort(__float2half_rn(go * tanh_fast(cst)));
      }
      if (isL && t + 1 < Tlen) {
        XB[rd][xb_ * PX + xi] = __half_as_ushort(__float2half_rn(xcur));
        xcur = xnext;
      }
      BARSYNC(1, 256);        // INT0: h0(t)+x(t+1) visible in group
      BARARR(3 + cur, 512);   // FULL: signal l1
    }
  } else {
    // ================= LAYER-1 GROUP =================
    u32 A1[2][8][4];
#pragma unroll
    for (int tt = 0; tt < 2; ++tt) {
      const int T = wl * 2 + tt;
      auto wrow = [&](int r) { return (r & 3) * 64 + T * 4 + (r >> 2); };
      auto ae = [&](int r, int k) -> float {
        int g = wrow(r);
        return (k < 64) ? Wih1[g * H + k] : Whh1[g * H + (k - 64)];
      };
#pragma unroll
      for (int kf = 0; kf < 8; ++kf) {
        const int c = kf * 16 + cq;
        A1[tt][kf][0] = pack2(ae(rq, c),         ae(rq, c + 1));
        A1[tt][kf][1] = pack2(ae(rq + 8, c),     ae(rq + 8, c + 1));
        A1[tt][kf][2] = pack2(ae(rq, c + 8),     ae(rq, c + 9));
        A1[tt][kf][3] = pack2(ae(rq + 8, c + 8), ae(rq + 8, c + 9));
      }
    }
    float cst = 0.0f;
    BARARR(5, 512);  // prime FREE[0]
    BARARR(6, 512);  // prime FREE[1]

#pragma unroll 1
    for (int t = 0; t < Tlen; ++t) {
      const int cur = t & 1, rd = cur ^ 1;
      BARSYNC(3 + cur, 512);  // FULL: h0(t) ready in slot cur
      u32 bf[8][2];
#pragma unroll
      for (int kf = 0; kf < 4; ++kf) ldsm_x2(bf[kf][0], bf[kf][1], h0a[cur] + kf * 32);
#pragma unroll
      for (int kf = 4; kf < 8; ++kf) ldsm_x2(bf[kf][0], bf[kf][1], h1a[rd] + (kf - 4) * 32);
      BARARR(5 + cur, 512);   // FREE: slot cur consumed

#pragma unroll
      for (int tt = 0; tt < 2; ++tt) {
        float r0 = 0.f, r1 = 0.f, r2 = 0.f, r3 = 0.f;
        float s0 = 0.f, s1 = 0.f, s2 = 0.f, s3 = 0.f;
#pragma unroll
        for (int q = 0; q < 4; ++q) {
          mma16816(r0, r1, r2, r3, A1[tt][q],     bf[q][0],     bf[q][1]);
          mma16816(s0, s1, s2, s3, A1[tt][q + 4], bf[q + 4][0], bf[q + 4][1]);
        }
        if ((lane & 3) < 2) {
          const int u = rq >> 2, g = rq & 3;
          GW[w][tt][u][cq][g]         = r0 + s0;
          GW[w][tt][u][cq + 1][g]     = r1 + s1;
          GW[w][tt][u + 2][cq][g]     = r2 + s2;
          GW[w][tt][u + 2][cq + 1][g] = r3 + s3;
        }
      }
      __syncwarp();
      const float4 gv = *reinterpret_cast<const float4*>(&GW[w][tt_][tu][tb][0]);
      {
        float gi = sigmoid_fast(gv.x + bq.x);
        float gf = sigmoid_fast(gv.y + bq.y);
        float gg = tanh_fast(gv.z + bq.z);
        float go = sigmoid_fast(gv.w + bq.w);
        cst = fmaf(gf, cst, gi * gg);
        float hv = go * tanh_fast(cst);
        if (t + 1 < Tlen) {
          H1B[cur][tb * PH + tj] = __half_as_ushort(__float2half_rn(hv));
        } else {
          H1F[tj * 4 + tb] = hv;
        }
      }
      BARSYNC(2, 256);        // INT1
    }
  }

  __syncthreads();
  if (tid < NB) {
    float acc = fcb[0];
#pragma unroll 16
    for (int j = 0; j < H; ++j) acc = fmaf(H1F[j * 4 + tid], FCW[j], acc);
    out[b0 + tid] = 1.0f / (1.0f + __expf(-acc));
  }
}

extern "C" void kernel_launch(void* const* d_in, const int* in_sizes, int n_in,
                              void* d_out, int out_size) {
  const float* x    = (const float*)d_in[0];
  const float* Wih0 = (const float*)d_in[1];
  const float* Whh0 = (const float*)d_in[2];
  const float* bih0 = (const float*)d_in[3];
  const float* bhh0 = (const float*)d_in[4];
  const float* Wih1 = (const float*)d_in[5];
  const float* Whh1 = (const float*)d_in[6];
  const float* bih1 = (const float*)d_in[7];
  const float* bhh1 = (const float*)d_in[8];
  const float* fcw  = (const float*)d_in[9];
  const float* fcb  = (const float*)d_in[10];
  float* out = (float*)d_out;

  lstm2_ws_kernel<<<NBLK, NTHR>>>(x, Wih0, Whh0, bih0, bhh0, Wih1, Whh1,
                                  bih1, bhh1, fcw, fcb, out);
}